// round 7
// baseline (speedup 1.0000x reference)
#include <cuda_runtime.h>
#include <cuda_fp16.h>
#include <cstdint>
#include <cstring>

#define BATCH 8192
#define INF   4096
#define OUTF  4096
#define SR    256
#define NSTG  64            // 64 K-chunks of 64
#define SMEM_DYN 98304      // 96 KB dynamic smem
#define SS_STRIDE 264       // padded fp32 row stride for the s-tile

// ---------------- W in fp16 (converted once per launch; 2 MB, static) ----------------
__device__ __align__(16) __half g_wh[SR * INF];

__device__ __forceinline__ uint32_t smem_u32_of(const void* p) {
    uint32_t a;
    asm("{ .reg .u64 t; cvta.to.shared.u64 t, %1; cvt.u32.u64 %0, t; }" : "=r"(a) : "l"(p));
    return a;
}

__device__ __forceinline__ uint32_t pack_h2(float a, float b) {
    __half2 h = __floats2half2_rn(a, b);
    uint32_t r; memcpy(&r, &h, 4); return r;
}

__global__ void __launch_bounds__(256) wconv_kernel(const float* __restrict__ w) {
    int i = blockIdx.x * 256 + threadIdx.x;       // float4 index, 262144 total
    float4 v = ((const float4*)w)[i];
    uint2 u;
    u.x = pack_h2(v.x, v.y);
    u.y = pack_h2(v.z, v.w);
    ((uint2*)g_wh)[i] = u;
}

// ---------------- fused GEMM (s = x @ W^T, fp16 HMMA) + broadcast epilogue ----------------
// grid = 128 CTAs (64 M-rows each), block = 256 (8 warps: 2 in M x 4 in N)
//
// SMEM map (dynamic, 96 KB):
//   [0      , 16384 )  A stage bufs  : 2 x (64 rows x 128 B)  fp16, SW-xor swizzled
//   [16384  , 81920 )  B stage bufs  : 2 x (256 rows x 128 B) fp16, swizzled
//   [81920  , 98304 )  bias (4096 fp32)
//   after mainloop, [0, 67584) is reused for the 64x256 fp32 s-tile (stride 264)
__global__ void __launch_bounds__(256, 1)
swfc_fused(const float* __restrict__ x, const float* __restrict__ bias,
           float* __restrict__ out)
{
    extern __shared__ char smem[];
    const uint32_t sb32 = smem_u32_of(smem);

    const int tid  = threadIdx.x;
    const int lane = tid & 31;
    const int wid  = tid >> 5;
    const int wm   = wid & 1;          // m offset 32*wm
    const int wn   = wid >> 1;         // n offset 64*wn
    const int m0   = blockIdx.x * 64;

    // stage bias into smem (used only in the epilogue, after many syncs)
    float* biass = (float*)(smem + 81920);
    #pragma unroll
    for (int j = 0; j < 4; ++j)
        ((float4*)biass)[tid + 256 * j] = ((const float4*)bias)[tid + 256 * j];

    // accumulators: per warp 32(M) x 64(N) = 2 m16-tiles x 8 n8-tiles
    float acc[2][8][4];
    #pragma unroll
    for (int mi = 0; mi < 2; ++mi)
        #pragma unroll
        for (int ni = 0; ni < 8; ++ni)
            #pragma unroll
            for (int q = 0; q < 4; ++q) acc[mi][ni][q] = 0.0f;

    // prefetch registers for the next stage
    float af[2][8];   // A: 2 units x 8 fp32
    uint4 bu[8];      // B: 8 units x 16B fp16

    auto load_regs = [&](int s) {
        const int kc = s * 64;
        #pragma unroll
        for (int j = 0; j < 2; ++j) {
            int idx = tid + j * 256;
            int r = idx >> 3, u = idx & 7;
            const float* p = x + (size_t)(m0 + r) * INF + kc + u * 8;
            float4 v0 = *(const float4*)p;
            float4 v1 = *(const float4*)(p + 4);
            af[j][0] = v0.x; af[j][1] = v0.y; af[j][2] = v0.z; af[j][3] = v0.w;
            af[j][4] = v1.x; af[j][5] = v1.y; af[j][6] = v1.z; af[j][7] = v1.w;
        }
        #pragma unroll
        for (int j = 0; j < 8; ++j) {
            int idx = tid + j * 256;
            int r = idx >> 3, u = idx & 7;
            bu[j] = *(const uint4*)(g_wh + (size_t)r * INF + kc + u * 8);
        }
    };

    auto store_regs = [&](int bs) {
        char* Ab = smem + bs * 8192;
        char* Bb = smem + 16384 + bs * 32768;
        #pragma unroll
        for (int j = 0; j < 2; ++j) {
            int idx = tid + j * 256;
            int r = idx >> 3, u = idx & 7;
            uint4 q;
            q.x = pack_h2(af[j][0], af[j][1]);
            q.y = pack_h2(af[j][2], af[j][3]);
            q.z = pack_h2(af[j][4], af[j][5]);
            q.w = pack_h2(af[j][6], af[j][7]);
            *(uint4*)(Ab + r * 128 + ((u ^ (r & 7)) << 4)) = q;
        }
        #pragma unroll
        for (int j = 0; j < 8; ++j) {
            int idx = tid + j * 256;
            int r = idx >> 3, u = idx & 7;
            *(uint4*)(Bb + r * 128 + ((u ^ (r & 7)) << 4)) = bu[j];
        }
    };

    // prologue
    load_regs(0);
    store_regs(0);
    __syncthreads();

    for (int s = 0; s < NSTG; ++s) {
        if (s + 1 < NSTG) load_regs(s + 1);   // global prefetch overlaps compute

        const uint32_t Ab32 = sb32 + (uint32_t)((s & 1) * 8192);
        const uint32_t Bb32 = sb32 + 16384u + (uint32_t)((s & 1) * 32768);

        #pragma unroll
        for (int ku = 0; ku < 4; ++ku) {
            // A fragments for both m16 tiles of this warp
            uint32_t afr[2][4];
            #pragma unroll
            for (int mi = 0; mi < 2; ++mi) {
                int row  = wm * 32 + mi * 16 + ((lane >> 3) & 1) * 8 + (lane & 7);
                int unit = ku * 2 + (lane >> 4);
                uint32_t addr = Ab32 + (uint32_t)(row * 128 + ((unit ^ (row & 7)) << 4));
                asm volatile("ldmatrix.sync.aligned.m8n8.x4.shared.b16 {%0,%1,%2,%3}, [%4];"
                    : "=r"(afr[mi][0]), "=r"(afr[mi][1]), "=r"(afr[mi][2]), "=r"(afr[mi][3])
                    : "r"(addr));
            }
            // B fragments: 4 x4-loads cover the warp's 8 n8-tiles
            #pragma unroll
            for (int gi = 0; gi < 4; ++gi) {
                int nrow = wn * 64 + gi * 16 + ((lane >> 4) & 1) * 8 + (lane & 7);
                int unit = ku * 2 + ((lane >> 3) & 1);
                uint32_t addr = Bb32 + (uint32_t)(nrow * 128 + ((unit ^ (nrow & 7)) << 4));
                uint32_t bf[4];
                asm volatile("ldmatrix.sync.aligned.m8n8.x4.shared.b16 {%0,%1,%2,%3}, [%4];"
                    : "=r"(bf[0]), "=r"(bf[1]), "=r"(bf[2]), "=r"(bf[3]) : "r"(addr));
                #pragma unroll
                for (int mi = 0; mi < 2; ++mi) {
                    asm volatile(
                        "mma.sync.aligned.m16n8k16.row.col.f32.f16.f16.f32 "
                        "{%0,%1,%2,%3}, {%4,%5,%6,%7}, {%8,%9}, {%0,%1,%2,%3};"
                        : "+f"(acc[mi][2 * gi][0]), "+f"(acc[mi][2 * gi][1]),
                          "+f"(acc[mi][2 * gi][2]), "+f"(acc[mi][2 * gi][3])
                        : "r"(afr[mi][0]), "r"(afr[mi][1]), "r"(afr[mi][2]), "r"(afr[mi][3]),
                          "r"(bf[0]), "r"(bf[1]));
                    asm volatile(
                        "mma.sync.aligned.m16n8k16.row.col.f32.f16.f16.f32 "
                        "{%0,%1,%2,%3}, {%4,%5,%6,%7}, {%8,%9}, {%0,%1,%2,%3};"
                        : "+f"(acc[mi][2 * gi + 1][0]), "+f"(acc[mi][2 * gi + 1][1]),
                          "+f"(acc[mi][2 * gi + 1][2]), "+f"(acc[mi][2 * gi + 1][3])
                        : "r"(afr[mi][0]), "r"(afr[mi][1]), "r"(afr[mi][2]), "r"(afr[mi][3]),
                          "r"(bf[2]), "r"(bf[3]));
                }
            }
        }
        __syncthreads();
        if (s + 1 < NSTG) {
            store_regs((s + 1) & 1);
            __syncthreads();
        }
    }

    // ---------------- s-tile (64 x 256 fp32) -> smem ----------------
    float* ss = (float*)smem;
    #pragma unroll
    for (int mi = 0; mi < 2; ++mi)
        #pragma unroll
        for (int ni = 0; ni < 8; ++ni) {
            int row = wm * 32 + mi * 16 + (lane >> 2);
            int col = wn * 64 + ni * 8 + (lane & 3) * 2;
            *(float2*)(ss + row * SS_STRIDE + col) =
                make_float2(acc[mi][ni][0], acc[mi][ni][1]);
            *(float2*)(ss + (row + 8) * SS_STRIDE + col) =
                make_float2(acc[mi][ni][2], acc[mi][ni][3]);
        }
    __syncthreads();

    // ---------------- epilogue: out[m, j] = s[m, j%256] + bias[j] ----------------
    // thread's 4 column-quads per row: c4 = tid + 256*r  (constant across rows)
    // s float4 per thread: s[row][(tid%64)*4 ..]          (constant across r)
    float4 bv[4];
    #pragma unroll
    for (int r = 0; r < 4; ++r) bv[r] = ((const float4*)biass)[tid + 256 * r];

    for (int row = 0; row < 64; ++row) {
        float4 sv = *(const float4*)(ss + row * SS_STRIDE + (tid & 63) * 4);
        float4* orow = (float4*)(out + (size_t)(m0 + row) * OUTF);
        #pragma unroll
        for (int r = 0; r < 4; ++r) {
            float4 o;
            o.x = sv.x + bv[r].x;
            o.y = sv.y + bv[r].y;
            o.z = sv.z + bv[r].z;
            o.w = sv.w + bv[r].w;
            orow[tid + 256 * r] = o;
        }
    }
}

// ---------------- launch ----------------
extern "C" void kernel_launch(void* const* d_in, const int* in_sizes, int n_in,
                              void* d_out, int out_size)
{
    const float* x    = (const float*)d_in[0];   // [8192, 4096] fp32
    const float* w    = (const float*)d_in[1];   // [256, 4096]  fp32
    const float* bias = (const float*)d_in[2];   // [4096]       fp32
    float* out = (float*)d_out;                  // [8192, 4096] fp32

    cudaFuncSetAttribute(swfc_fused, cudaFuncAttributeMaxDynamicSharedMemorySize, SMEM_DYN);

    wconv_kernel<<<1024, 256>>>(w);              // W fp32 -> fp16 (2 MB, stays in L2)
    swfc_fused<<<128, 256, SMEM_DYN>>>(x, bias, out);
}

// round 8
// speedup vs baseline: 1.0094x; 1.0094x over previous
#include <cuda_runtime.h>
#include <cuda_fp16.h>
#include <cstdint>
#include <cstring>

#define BATCH 8192
#define INF   4096
#define OUTF  4096
#define SR    256
#define NSTG  64            // 64 K-chunks of 64
#define SMEM_DYN 98304      // 96 KB dynamic smem
#define SS_STRIDE 264       // padded fp32 row stride for the s-tile

// ---------------- W in fp16 (converted once per launch; 2 MB, static) ----------------
__device__ __align__(16) __half g_wh[SR * INF];

__device__ __forceinline__ uint32_t smem_u32_of(const void* p) {
    uint32_t a;
    asm("{ .reg .u64 t; cvta.to.shared.u64 t, %1; cvt.u32.u64 %0, t; }" : "=r"(a) : "l"(p));
    return a;
}

__device__ __forceinline__ uint32_t pack_h2(float a, float b) {
    __half2 h = __floats2half2_rn(a, b);
    uint32_t r; memcpy(&r, &h, 4); return r;
}

__global__ void __launch_bounds__(256) wconv_kernel(const float* __restrict__ w) {
    int i = blockIdx.x * 256 + threadIdx.x;       // float4 index, 262144 total
    float4 v = ((const float4*)w)[i];
    uint2 u;
    u.x = pack_h2(v.x, v.y);
    u.y = pack_h2(v.z, v.w);
    ((uint2*)g_wh)[i] = u;
}

// ---------------- fused GEMM (s = x @ W^T, fp16 HMMA) + broadcast epilogue ----------------
// grid = 128 CTAs (64 M-rows each), block = 256 (8 warps: 2 in M x 4 in N)
//
// SMEM map (dynamic, 96 KB):
//   [0      , 16384 )  A stage bufs  : 2 x (64 rows x 128 B)  fp16, SW-xor swizzled
//   [16384  , 81920 )  B stage bufs  : 2 x (256 rows x 128 B) fp16, swizzled
//   [81920  , 98304 )  bias (4096 fp32)
//   after mainloop, [0, 67584) is reused for the 64x256 fp32 s-tile (stride 264)
__global__ void __launch_bounds__(256, 1)
swfc_fused(const float* __restrict__ x, const float* __restrict__ bias,
           float* __restrict__ out)
{
    extern __shared__ char smem[];
    const uint32_t sb32 = smem_u32_of(smem);

    const int tid  = threadIdx.x;
    const int lane = tid & 31;
    const int wid  = tid >> 5;
    const int wm   = wid & 1;          // m offset 32*wm
    const int wn   = wid >> 1;         // n offset 64*wn
    const int m0   = blockIdx.x * 64;

    // stage bias into smem (used only in the epilogue, after many syncs)
    float* biass = (float*)(smem + 81920);
    #pragma unroll
    for (int j = 0; j < 4; ++j)
        ((float4*)biass)[tid + 256 * j] = ((const float4*)bias)[tid + 256 * j];

    // accumulators: per warp 32(M) x 64(N) = 2 m16-tiles x 8 n8-tiles
    float acc[2][8][4];
    #pragma unroll
    for (int mi = 0; mi < 2; ++mi)
        #pragma unroll
        for (int ni = 0; ni < 8; ++ni)
            #pragma unroll
            for (int q = 0; q < 4; ++q) acc[mi][ni][q] = 0.0f;

    // prefetch registers for the next stage
    float af[2][8];   // A: 2 units x 8 fp32
    uint4 bu[8];      // B: 8 units x 16B fp16

    auto load_regs = [&](int s) {
        const int kc = s * 64;
        #pragma unroll
        for (int j = 0; j < 2; ++j) {
            int idx = tid + j * 256;
            int r = idx >> 3, u = idx & 7;
            const float* p = x + (size_t)(m0 + r) * INF + kc + u * 8;
            float4 v0 = *(const float4*)p;
            float4 v1 = *(const float4*)(p + 4);
            af[j][0] = v0.x; af[j][1] = v0.y; af[j][2] = v0.z; af[j][3] = v0.w;
            af[j][4] = v1.x; af[j][5] = v1.y; af[j][6] = v1.z; af[j][7] = v1.w;
        }
        #pragma unroll
        for (int j = 0; j < 8; ++j) {
            int idx = tid + j * 256;
            int r = idx >> 3, u = idx & 7;
            bu[j] = *(const uint4*)(g_wh + (size_t)r * INF + kc + u * 8);
        }
    };

    auto store_regs = [&](int bs) {
        char* Ab = smem + bs * 8192;
        char* Bb = smem + 16384 + bs * 32768;
        #pragma unroll
        for (int j = 0; j < 2; ++j) {
            int idx = tid + j * 256;
            int r = idx >> 3, u = idx & 7;
            uint4 q;
            q.x = pack_h2(af[j][0], af[j][1]);
            q.y = pack_h2(af[j][2], af[j][3]);
            q.z = pack_h2(af[j][4], af[j][5]);
            q.w = pack_h2(af[j][6], af[j][7]);
            *(uint4*)(Ab + r * 128 + ((u ^ (r & 7)) << 4)) = q;
        }
        #pragma unroll
        for (int j = 0; j < 8; ++j) {
            int idx = tid + j * 256;
            int r = idx >> 3, u = idx & 7;
            *(uint4*)(Bb + r * 128 + ((u ^ (r & 7)) << 4)) = bu[j];
        }
    };

    // prologue
    load_regs(0);
    store_regs(0);
    __syncthreads();

    for (int s = 0; s < NSTG; ++s) {
        if (s + 1 < NSTG) load_regs(s + 1);   // global prefetch overlaps compute

        const uint32_t Ab32 = sb32 + (uint32_t)((s & 1) * 8192);
        const uint32_t Bb32 = sb32 + 16384u + (uint32_t)((s & 1) * 32768);

        #pragma unroll
        for (int ku = 0; ku < 4; ++ku) {
            // A fragments for both m16 tiles of this warp
            uint32_t afr[2][4];
            #pragma unroll
            for (int mi = 0; mi < 2; ++mi) {
                int row  = wm * 32 + mi * 16 + ((lane >> 3) & 1) * 8 + (lane & 7);
                int unit = ku * 2 + (lane >> 4);
                uint32_t addr = Ab32 + (uint32_t)(row * 128 + ((unit ^ (row & 7)) << 4));
                asm volatile("ldmatrix.sync.aligned.m8n8.x4.shared.b16 {%0,%1,%2,%3}, [%4];"
                    : "=r"(afr[mi][0]), "=r"(afr[mi][1]), "=r"(afr[mi][2]), "=r"(afr[mi][3])
                    : "r"(addr));
            }
            // B fragments: 4 x4-loads cover the warp's 8 n8-tiles
            #pragma unroll
            for (int gi = 0; gi < 4; ++gi) {
                int nrow = wn * 64 + gi * 16 + ((lane >> 4) & 1) * 8 + (lane & 7);
                int unit = ku * 2 + ((lane >> 3) & 1);
                uint32_t addr = Bb32 + (uint32_t)(nrow * 128 + ((unit ^ (nrow & 7)) << 4));
                uint32_t bf[4];
                asm volatile("ldmatrix.sync.aligned.m8n8.x4.shared.b16 {%0,%1,%2,%3}, [%4];"
                    : "=r"(bf[0]), "=r"(bf[1]), "=r"(bf[2]), "=r"(bf[3]) : "r"(addr));
                #pragma unroll
                for (int mi = 0; mi < 2; ++mi) {
                    asm volatile(
                        "mma.sync.aligned.m16n8k16.row.col.f32.f16.f16.f32 "
                        "{%0,%1,%2,%3}, {%4,%5,%6,%7}, {%8,%9}, {%0,%1,%2,%3};"
                        : "+f"(acc[mi][2 * gi][0]), "+f"(acc[mi][2 * gi][1]),
                          "+f"(acc[mi][2 * gi][2]), "+f"(acc[mi][2 * gi][3])
                        : "r"(afr[mi][0]), "r"(afr[mi][1]), "r"(afr[mi][2]), "r"(afr[mi][3]),
                          "r"(bf[0]), "r"(bf[1]));
                    asm volatile(
                        "mma.sync.aligned.m16n8k16.row.col.f32.f16.f16.f32 "
                        "{%0,%1,%2,%3}, {%4,%5,%6,%7}, {%8,%9}, {%0,%1,%2,%3};"
                        : "+f"(acc[mi][2 * gi + 1][0]), "+f"(acc[mi][2 * gi + 1][1]),
                          "+f"(acc[mi][2 * gi + 1][2]), "+f"(acc[mi][2 * gi + 1][3])
                        : "r"(afr[mi][0]), "r"(afr[mi][1]), "r"(afr[mi][2]), "r"(afr[mi][3]),
                          "r"(bf[2]), "r"(bf[3]));
                }
            }
        }
        __syncthreads();
        if (s + 1 < NSTG) {
            store_regs((s + 1) & 1);
            __syncthreads();
        }
    }

    // ---------------- s-tile (64 x 256 fp32) -> smem ----------------
    float* ss = (float*)smem;
    #pragma unroll
    for (int mi = 0; mi < 2; ++mi)
        #pragma unroll
        for (int ni = 0; ni < 8; ++ni) {
            int row = wm * 32 + mi * 16 + (lane >> 2);
            int col = wn * 64 + ni * 8 + (lane & 3) * 2;
            *(float2*)(ss + row * SS_STRIDE + col) =
                make_float2(acc[mi][ni][0], acc[mi][ni][1]);
            *(float2*)(ss + (row + 8) * SS_STRIDE + col) =
                make_float2(acc[mi][ni][2], acc[mi][ni][3]);
        }
    __syncthreads();

    // ---------------- epilogue: out[m, j] = s[m, j%256] + bias[j] ----------------
    // thread's 4 column-quads per row: c4 = tid + 256*r  (constant across rows)
    // s float4 per thread: s[row][(tid%64)*4 ..]          (constant across r)
    float4 bv[4];
    #pragma unroll
    for (int r = 0; r < 4; ++r) bv[r] = ((const float4*)biass)[tid + 256 * r];

    for (int row = 0; row < 64; ++row) {
        float4 sv = *(const float4*)(ss + row * SS_STRIDE + (tid & 63) * 4);
        float4* orow = (float4*)(out + (size_t)(m0 + row) * OUTF);
        #pragma unroll
        for (int r = 0; r < 4; ++r) {
            float4 o;
            o.x = sv.x + bv[r].x;
            o.y = sv.y + bv[r].y;
            o.z = sv.z + bv[r].z;
            o.w = sv.w + bv[r].w;
            orow[tid + 256 * r] = o;
        }
    }
}

// ---------------- launch ----------------
extern "C" void kernel_launch(void* const* d_in, const int* in_sizes, int n_in,
                              void* d_out, int out_size)
{
    const float* x    = (const float*)d_in[0];   // [8192, 4096] fp32
    const float* w    = (const float*)d_in[1];   // [256, 4096]  fp32
    const float* bias = (const float*)d_in[2];   // [4096]       fp32
    float* out = (float*)d_out;                  // [8192, 4096] fp32

    cudaFuncSetAttribute(swfc_fused, cudaFuncAttributeMaxDynamicSharedMemorySize, SMEM_DYN);

    wconv_kernel<<<1024, 256>>>(w);              // W fp32 -> fp16 (2 MB, stays in L2)
    swfc_fused<<<128, 256, SMEM_DYN>>>(x, bias, out);
}

// round 9
// speedup vs baseline: 1.0574x; 1.0475x over previous
#include <cuda_runtime.h>
#include <cuda_fp16.h>
#include <cstdint>
#include <cstring>

#define BATCH 8192
#define INF   4096
#define OUTF  4096
#define SR    256
#define NSTG  64             // 64 K-chunks of 64
#define STAGES 4

// SMEM layout (dynamic):
//   A bufs: 4 stages x (64 rows x 288 B fp32, padded stride 72 floats) = 73728
//   B bufs: 4 stages x (256 rows x 128 B fp16, XOR-swizzled)          = 131072 @ 73728
//   bias  : 16384 fp32 bytes                                           @ 204800
#define A_STG_BYTES 18432u
#define A_ROW_F     72
#define B_OFF       73728u
#define B_STG_BYTES 32768u
#define BIAS_OFF    204800u
#define SMEM_DYN    221184u
#define SS_STRIDE   264      // padded fp32 stride for the final s-tile

// ---------------- W in fp16 (converted once per launch; 2 MB, static) ----------------
__device__ __align__(16) __half g_wh[SR * INF];

__device__ __forceinline__ uint32_t smem_u32_of(const void* p) {
    uint32_t a;
    asm("{ .reg .u64 t; cvta.to.shared.u64 t, %1; cvt.u32.u64 %0, t; }" : "=r"(a) : "l"(p));
    return a;
}

__device__ __forceinline__ uint32_t pack_h2(float a, float b) {
    __half2 h = __floats2half2_rn(a, b);
    uint32_t r; memcpy(&r, &h, 4); return r;
}

__global__ void __launch_bounds__(256) wconv_kernel(const float* __restrict__ w) {
    int i = blockIdx.x * 256 + threadIdx.x;       // float4 index, 262144 total
    float4 v = ((const float4*)w)[i];
    uint2 u;
    u.x = pack_h2(v.x, v.y);
    u.y = pack_h2(v.z, v.w);
    ((uint2*)g_wh)[i] = u;
}

#define CP_ASYNC16(dst, src) \
    asm volatile("cp.async.cg.shared.global [%0], [%1], 16;" :: "r"(dst), "l"(src))
#define CP_COMMIT()  asm volatile("cp.async.commit_group;" ::: "memory")
#define CP_WAIT(n)   asm volatile("cp.async.wait_group %0;" :: "n"(n) : "memory")

// ---------------- fused GEMM (s = x @ W^T, fp16 HMMA) + broadcast epilogue ----------------
// grid = 128 CTAs (64 M-rows each), block = 256 (8 warps: 2 in M x 4 in N)
__global__ void __launch_bounds__(256, 1)
swfc_fused(const float* __restrict__ x, const float* __restrict__ bias,
           float* __restrict__ out)
{
    extern __shared__ char smem[];
    const uint32_t sb32 = smem_u32_of(smem);

    const int tid  = threadIdx.x;
    const int lane = tid & 31;
    const int wid  = tid >> 5;
    const int wm   = wid & 1;          // m offset 32*wm
    const int wn   = wid >> 1;         // n offset 64*wn
    const int m0   = blockIdx.x * 64;

    // stage bias into smem (consumed after many barriers; separate region)
    float* biass = (float*)(smem + BIAS_OFF);
    #pragma unroll
    for (int j = 0; j < 4; ++j)
        ((float4*)biass)[tid + 256 * j] = ((const float4*)bias)[tid + 256 * j];

    // accumulators: per warp 32(M) x 64(N) = 2 m16-tiles x 8 n8-tiles
    float acc[2][8][4];
    #pragma unroll
    for (int mi = 0; mi < 2; ++mi)
        #pragma unroll
        for (int ni = 0; ni < 8; ++ni)
            #pragma unroll
            for (int q = 0; q < 4; ++q) acc[mi][ni][q] = 0.0f;

    // ---- async producer: stage s -> buffer s&3 ----
    auto issue = [&](int s) {
        const int stg = s & (STAGES - 1);
        const int kc  = s * 64;
        const uint32_t As = sb32 + (uint32_t)stg * A_STG_BYTES;
        const uint32_t Bs = sb32 + B_OFF + (uint32_t)stg * B_STG_BYTES;
        // A: 64 rows x 64 fp32 = 1024 x 16B chunks (4 per thread)
        #pragma unroll
        for (int j = 0; j < 4; ++j) {
            int idx = tid + j * 256;
            int r = idx >> 4, u = idx & 15;
            const float* src = x + (size_t)(m0 + r) * INF + kc + u * 4;
            CP_ASYNC16(As + (uint32_t)(r * (A_ROW_F * 4) + u * 16), src);
        }
        // B: 256 rows x 64 fp16 = 2048 x 16B chunks (8 per thread), XOR swizzle
        #pragma unroll
        for (int j = 0; j < 8; ++j) {
            int idx = tid + j * 256;
            int r = idx >> 3, u = idx & 7;
            const __half* src = g_wh + (size_t)r * INF + kc + u * 8;
            CP_ASYNC16(Bs + (uint32_t)(r * 128 + ((u ^ (r & 7)) << 4)), src);
        }
    };

    // prologue: 3 stages in flight
    issue(0); CP_COMMIT();
    issue(1); CP_COMMIT();
    issue(2); CP_COMMIT();

    const int gr  = lane >> 2;
    const int gc2 = (lane & 3) * 2;

    for (int s = 0; s < NSTG; ++s) {
        CP_WAIT(2);            // this thread's stage-s copies complete
        __syncthreads();       // everyone's complete -> stage s visible; buf (s-1)&3 free
        if (s + 3 < NSTG) issue(s + 3);
        CP_COMMIT();           // empty groups in the tail keep accounting uniform

        const int stg = s & (STAGES - 1);
        const float*  Af   = (const float*)(smem + stg * A_STG_BYTES);
        const uint32_t Bs32 = sb32 + B_OFF + (uint32_t)stg * B_STG_BYTES;

        #pragma unroll
        for (int ku = 0; ku < 4; ++ku) {
            // A fragments built from fp32 smem (LDS.64 + cvt.f16x2)
            uint32_t afr[2][4];
            #pragma unroll
            for (int mi = 0; mi < 2; ++mi) {
                const float* p = Af + (wm * 32 + mi * 16 + gr) * A_ROW_F + ku * 16 + gc2;
                float2 f0 = *(const float2*)p;
                float2 f1 = *(const float2*)(p + 8 * A_ROW_F);
                float2 f2 = *(const float2*)(p + 8);
                float2 f3 = *(const float2*)(p + 8 * A_ROW_F + 8);
                afr[mi][0] = pack_h2(f0.x, f0.y);
                afr[mi][1] = pack_h2(f1.x, f1.y);
                afr[mi][2] = pack_h2(f2.x, f2.y);
                afr[mi][3] = pack_h2(f3.x, f3.y);
            }
            // B fragments via ldmatrix (proven path), then HMMA
            #pragma unroll
            for (int gi = 0; gi < 4; ++gi) {
                int nrow = wn * 64 + gi * 16 + ((lane >> 4) & 1) * 8 + (lane & 7);
                int unit = ku * 2 + ((lane >> 3) & 1);
                uint32_t addr = Bs32 + (uint32_t)(nrow * 128 + ((unit ^ (nrow & 7)) << 4));
                uint32_t bf[4];
                asm volatile("ldmatrix.sync.aligned.m8n8.x4.shared.b16 {%0,%1,%2,%3}, [%4];"
                    : "=r"(bf[0]), "=r"(bf[1]), "=r"(bf[2]), "=r"(bf[3]) : "r"(addr));
                #pragma unroll
                for (int mi = 0; mi < 2; ++mi) {
                    asm volatile(
                        "mma.sync.aligned.m16n8k16.row.col.f32.f16.f16.f32 "
                        "{%0,%1,%2,%3}, {%4,%5,%6,%7}, {%8,%9}, {%0,%1,%2,%3};"
                        : "+f"(acc[mi][2 * gi][0]), "+f"(acc[mi][2 * gi][1]),
                          "+f"(acc[mi][2 * gi][2]), "+f"(acc[mi][2 * gi][3])
                        : "r"(afr[mi][0]), "r"(afr[mi][1]), "r"(afr[mi][2]), "r"(afr[mi][3]),
                          "r"(bf[0]), "r"(bf[1]));
                    asm volatile(
                        "mma.sync.aligned.m16n8k16.row.col.f32.f16.f16.f32 "
                        "{%0,%1,%2,%3}, {%4,%5,%6,%7}, {%8,%9}, {%0,%1,%2,%3};"
                        : "+f"(acc[mi][2 * gi + 1][0]), "+f"(acc[mi][2 * gi + 1][1]),
                          "+f"(acc[mi][2 * gi + 1][2]), "+f"(acc[mi][2 * gi + 1][3])
                        : "r"(afr[mi][0]), "r"(afr[mi][1]), "r"(afr[mi][2]), "r"(afr[mi][3]),
                          "r"(bf[2]), "r"(bf[3]));
                }
            }
        }
    }

    CP_WAIT(0);
    __syncthreads();

    // ---------------- s-tile (64 x 256 fp32) -> smem ----------------
    float* ss = (float*)smem;
    #pragma unroll
    for (int mi = 0; mi < 2; ++mi)
        #pragma unroll
        for (int ni = 0; ni < 8; ++ni) {
            int row = wm * 32 + mi * 16 + (lane >> 2);
            int col = wn * 64 + ni * 8 + (lane & 3) * 2;
            *(float2*)(ss + row * SS_STRIDE + col) =
                make_float2(acc[mi][ni][0], acc[mi][ni][1]);
            *(float2*)(ss + (row + 8) * SS_STRIDE + col) =
                make_float2(acc[mi][ni][2], acc[mi][ni][3]);
        }
    __syncthreads();

    // ---------------- epilogue: out[m, j] = s[m, j%256] + bias[j] ----------------
    float4 bv[4];
    #pragma unroll
    for (int r = 0; r < 4; ++r) bv[r] = ((const float4*)biass)[tid + 256 * r];

    for (int row = 0; row < 64; ++row) {
        float4 sv = *(const float4*)(ss + row * SS_STRIDE + (tid & 63) * 4);
        float4* orow = (float4*)(out + (size_t)(m0 + row) * OUTF);
        #pragma unroll
        for (int r = 0; r < 4; ++r) {
            float4 o;
            o.x = sv.x + bv[r].x;
            o.y = sv.y + bv[r].y;
            o.z = sv.z + bv[r].z;
            o.w = sv.w + bv[r].w;
            orow[tid + 256 * r] = o;
        }
    }
}

// ---------------- launch ----------------
extern "C" void kernel_launch(void* const* d_in, const int* in_sizes, int n_in,
                              void* d_out, int out_size)
{
    const float* x    = (const float*)d_in[0];   // [8192, 4096] fp32
    const float* w    = (const float*)d_in[1];   // [256, 4096]  fp32
    const float* bias = (const float*)d_in[2];   // [4096]       fp32
    float* out = (float*)d_out;                  // [8192, 4096] fp32

    cudaFuncSetAttribute(swfc_fused, cudaFuncAttributeMaxDynamicSharedMemorySize, SMEM_DYN);

    wconv_kernel<<<1024, 256>>>(w);              // W fp32 -> fp16 (2 MB, stays in L2)
    swfc_fused<<<128, 256, SMEM_DYN>>>(x, bias, out);
}